// round 11
// baseline (speedup 1.0000x reference)
#include <cuda_runtime.h>
#include <cuda_fp16.h>
#include <cstdint>

// Problem constants
#define N_B   4
#define C_IN  256
#define H_IM  64
#define W_IM  64
#define OC    256
#define K2    9
#define OMC   27
#define HW    (H_IM*W_IM)        // 4096
#define NPIX  (N_B*HW)           // 16384
#define KDIM  (C_IN*K2)          // 2304
#define NCHK  (KDIM/32)          // 72
#define NT64  (NPIX/64)          // 256 tiles of 64 px

// ---------------- device scratch ----------------
__device__ float  g_om  [(size_t)N_B * OMC * HW];
__device__ __half g_xth [(size_t)NPIX * C_IN];          // x transposed fp16: [n][hw][c]
__device__ __half g_colA[(size_t)NT64 * NCHK * 2048];   // im2col: [tile64][ch][32x64], SW128
__device__ __half g_wtB [(size_t)NCHK * 8192];          // dcn weights, pre-swizzled
__device__ __half g_owB [(size_t)NCHK * 1024];          // offset weights, pre-swizzled

__device__ __host__ __forceinline__ uint32_t swz64(uint32_t a) {
    return a ^ (((a >> 7) & 3u) << 4);
}
// SW128 swizzle for 128B-pitch rows (A tiles, 32kc x 64px fp16)
__device__ __host__ __forceinline__ uint32_t swz128(uint32_t a) {
    return a ^ (((a >> 7) & 7u) << 4);
}

__device__ __forceinline__ void sts16(uint32_t addr, unsigned short v) {
    asm volatile("st.shared.u16 [%0], %1;" :: "r"(addr), "h"(v));
}
__device__ __forceinline__ void sts32(uint32_t addr, uint32_t v) {
    asm volatile("st.shared.u32 [%0], %1;" :: "r"(addr), "r"(v));
}
__device__ __forceinline__ uint32_t lds32(uint32_t addr) {
    uint32_t v;
    asm volatile("ld.shared.b32 %0, [%1];" : "=r"(v) : "r"(addr));
    return v;
}
__device__ __forceinline__ void ldmx4(uint32_t* r, uint32_t addr) {
    asm volatile("ldmatrix.sync.aligned.m8n8.x4.shared.b16 {%0,%1,%2,%3}, [%4];"
        : "=r"(r[0]), "=r"(r[1]), "=r"(r[2]), "=r"(r[3]) : "r"(addr));
}
__device__ __forceinline__ void ldmx4t(uint32_t* r, uint32_t addr) {
    asm volatile("ldmatrix.sync.aligned.m8n8.x4.trans.shared.b16 {%0,%1,%2,%3}, [%4];"
        : "=r"(r[0]), "=r"(r[1]), "=r"(r[2]), "=r"(r[3]) : "r"(addr));
}
__device__ __forceinline__ void mma_f16(float* c, const uint32_t* a, const uint32_t* b) {
    asm volatile(
        "mma.sync.aligned.m16n8k16.row.col.f32.f16.f16.f32 "
        "{%0,%1,%2,%3}, {%4,%5,%6,%7}, {%8,%9}, {%0,%1,%2,%3};"
        : "+f"(c[0]), "+f"(c[1]), "+f"(c[2]), "+f"(c[3])
        : "r"(a[0]), "r"(a[1]), "r"(a[2]), "r"(a[3]), "r"(b[0]), "r"(b[1]));
}
__device__ __forceinline__ uint32_t prmt(uint32_t a, uint32_t b, uint32_t sel) {
    uint32_t d;
    asm("prmt.b32 %0, %1, %2, %3;" : "=r"(d) : "r"(a), "r"(b), "r"(sel));
    return d;
}

// ---------------------------------------------------------------------------
// Prep: pack both weight tensors (fp16, chunk-major, pre-swizzled).
// ---------------------------------------------------------------------------
__global__ void prep_kernel(const float* __restrict__ dw,
                            const float* __restrict__ ow)
{
    if (blockIdx.x < 256) {
        int oc = blockIdx.x;
        int c  = threadIdx.x;
        #pragma unroll
        for (int k = 0; k < 9; k++) {
            float w = dw[((size_t)oc * C_IN + c) * K2 + k];
            int ch  = k * 8 + (c >> 5);
            int kcl = c & 31;
            uint32_t raw = (uint32_t)oc * 64 + kcl * 2;
            g_wtB[(size_t)ch * 8192 + (swz64(raw) >> 1)] = __float2half_rn(w);
        }
    } else {
        int ch = blockIdx.x - 256;
        int k  = ch >> 3;
        int c0 = (ch & 7) * 32;
        #pragma unroll
        for (int it = 0; it < 4; it++) {
            int idx = threadIdx.x + it * 256;
            int oc = idx >> 5, kcl = idx & 31;
            float w = (oc < OMC)
                ? ow[((size_t)oc * C_IN + c0 + kcl) * K2 + k] : 0.f;
            uint32_t raw = (uint32_t)oc * 64 + kcl * 2;
            g_owB[(size_t)ch * 1024 + (swz64(raw) >> 1)] = __float2half_rn(w);
        }
    }
}

// ---------------------------------------------------------------------------
// Transpose x [n][c][hw] -> g_xth [n][hw][c] (fp16)
// ---------------------------------------------------------------------------
__global__ void transpose_x_kernel(const float* __restrict__ x)
{
    __shared__ float ts[64][65];
    const int hw0 = blockIdx.x * 64, c0 = blockIdx.y * 64, n = blockIdx.z;
    const float* xn = x + ((size_t)(n * C_IN + c0) << 12) + hw0;
    for (int i = threadIdx.x; i < 64 * 64; i += 256) {
        int r = i >> 6, col = i & 63;
        ts[r][col] = xn[((size_t)r << 12) + col];
    }
    __syncthreads();
    __half* xtn = g_xth + (((size_t)n << 12) + hw0) * C_IN + c0;
    for (int i = threadIdx.x; i < 64 * 64; i += 256) {
        int r = i >> 6, col = i & 63;
        xtn[(size_t)r * C_IN + col] = __float2half_rn(ts[col][r]);
    }
}

// ---------------------------------------------------------------------------
// Offset conv as fp16 implicit GEMM (unchanged from R8)
// ---------------------------------------------------------------------------
#define CV_APITCH 272
#define CV_A_SZ   (32 * CV_APITCH)
#define CV_B_SZ   2048
#define CV_STG    (CV_A_SZ + CV_B_SZ)

__global__ void __launch_bounds__(256, 1) conv_gemm_kernel(
    const float* __restrict__ x, const float* __restrict__ ob)
{
    __shared__ char sm[2 * CV_STG];
    const uint32_t sb = (uint32_t)__cvta_generic_to_shared(sm);
    const int tid = threadIdx.x;
    const int wid = tid >> 5, lid = tid & 31;
    const int bm0 = blockIdx.x * 128;
    const int nIdx = bm0 >> 12, hwb = bm0 & 4095, ho0 = hwb >> 6;
    const float* xn = x + ((size_t)nIdx * C_IN << 12);

    const int p = tid & 127;
    const int kcl0 = tid >> 7;
    const int pho = p >> 6, pwo = p & 63;

    float acc[4][4];
    #pragma unroll
    for (int j = 0; j < 4; j++)
        #pragma unroll
        for (int q = 0; q < 4; q++) acc[j][q] = 0.f;

    auto build = [&](int ch, int st) {
        const int k = ch >> 3, c0 = (ch & 7) * 32;
        const int dy = k / 3 - 1, dx = k % 3 - 1;
        const int hy = ho0 + pho + dy;
        const int wx = pwo + dx;
        const bool v = ((unsigned)hy < 64u) && ((unsigned)wx < 64u);
        const float* src = xn + ((size_t)(c0 + kcl0) << 12) + (hy << 6) + wx;
        const uint32_t dst = sb + st * CV_STG + kcl0 * CV_APITCH + p * 2;
        #pragma unroll
        for (int it = 0; it < 16; it++) {
            float val = 0.f;
            if (v) val = src[(size_t)(it * 2) << 12];
            sts16(dst + it * 2 * CV_APITCH,
                  __half_as_ushort(__float2half_rn(val)));
        }
        if (tid < 128) {
            const uint4* bsrc = (const uint4*)(g_owB + (size_t)ch * 1024);
            *(uint4*)(sm + st * CV_STG + CV_A_SZ + tid * 16) = bsrc[tid];
        }
    };

    const int qq = lid >> 3, jr = lid & 7;
    const uint32_t aoff = (uint32_t)(((qq >> 1) * 8 + jr) * CV_APITCH
                                     + (wid * 16 + (qq & 1) * 8) * 2);
    const int oc_l = (qq >> 1) * 8 + jr;

    build(0, 0);
    __syncthreads();

    for (int ch = 0; ch < NCHK; ch++) {
        const int st = ch & 1;
        if (ch + 1 < NCHK) build(ch + 1, st ^ 1);

        const uint32_t ab = sb + st * CV_STG;
        const uint32_t bb = ab + CV_A_SZ;
        #pragma unroll
        for (int kp = 0; kp < 2; kp++) {
            uint32_t Af[4];
            ldmx4t(Af, ab + aoff + kp * (16 * CV_APITCH));
            #pragma unroll
            for (int pi = 0; pi < 2; pi++) {
                uint32_t Bf[4];
                uint32_t raw = (uint32_t)(oc_l + pi * 16) * 64
                             + (kp * 2 + (qq & 1)) * 16;
                ldmx4(Bf, bb + swz64(raw));
                mma_f16(acc[pi*2],   Af, &Bf[0]);
                mma_f16(acc[pi*2+1], Af, &Bf[2]);
            }
        }
        __syncthreads();
    }

    float* T = (float*)sm;
    const int r0 = wid * 16 + (lid >> 2);
    #pragma unroll
    for (int jj = 0; jj < 4; jj++) {
        int oc = jj * 8 + (lid & 3) * 2;
        T[ oc      * 136 + r0    ] = acc[jj][0];
        T[(oc + 1) * 136 + r0    ] = acc[jj][1];
        T[ oc      * 136 + r0 + 8] = acc[jj][2];
        T[(oc + 1) * 136 + r0 + 8] = acc[jj][3];
    }
    __syncthreads();
    for (int idx = tid; idx < OMC * 128; idx += 256) {
        int o = idx >> 7, m = idx & 127;
        g_om[((size_t)(nIdx * OMC + o) << 12) + hwb + m] = T[o * 136 + m] + ob[o];
    }
}

// ---------------------------------------------------------------------------
// Sampling v4: half2 channel-major gathers from g_xth.
// grid (256 tiles64, 9 taps), 256 threads = 8 warps.
// Warp w: ch-group g = w&3 (64 channels, lane = half2 pair), px-half ph = w>>2.
// ---------------------------------------------------------------------------
__global__ void __launch_bounds__(256, 5) sample4_kernel()
{
    __shared__ float4 sW[64];
    __shared__ int4   sI[64];                 // byte offsets (hw * 512)
    __shared__ char   stg[8 * 4224];          // per-warp [32 pairs][33 u32]

    const int tile = blockIdx.x;              // 64-px tile
    const int k    = blockIdx.y;              // tap
    const int n    = tile >> 6;
    const int hw0  = (tile & 63) * 64;
    const int tid  = threadIdx.x;

    // ---- phase 1: bilinear weights + corner byte-offsets for 64 px ----
    const float* omn = g_om + (size_t)n * OMC * HW;
    if (tid < 64) {
        int pl = tid;
        int p = hw0 + pl;
        int ho = p >> 6, wo = p & 63;

        float oy = omn[((size_t)(2*k    ) << 12) + p];
        float ox = omn[((size_t)(2*k + 1) << 12) + p];
        float mv = omn[((size_t)(18 + k ) << 12) + p];
        float m  = 1.0f / (1.0f + expf(-mv));

        float him = (float)(ho + (k / 3) - 1) + oy;
        float wim = (float)(wo + (k % 3) - 1) + ox;

        float y0 = floorf(him), x0 = floorf(wim);
        float lh = him - y0,    lw = wim - x0;
        float hh = 1.0f - lh,   hw = 1.0f - lw;
        float y1 = y0 + 1.0f,   x1 = x0 + 1.0f;

        float vy0 = (y0 >= 0.f && y0 <= 63.f) ? 1.f : 0.f;
        float vy1 = (y1 >= 0.f && y1 <= 63.f) ? 1.f : 0.f;
        float vx0 = (x0 >= 0.f && x0 <= 63.f) ? 1.f : 0.f;
        float vx1 = (x1 >= 0.f && x1 <= 63.f) ? 1.f : 0.f;

        int iy0 = (int)fminf(fmaxf(y0, 0.f), 63.f);
        int iy1 = (int)fminf(fmaxf(y1, 0.f), 63.f);
        int ix0 = (int)fminf(fmaxf(x0, 0.f), 63.f);
        int ix1 = (int)fminf(fmaxf(x1, 0.f), 63.f);

        sW[pl] = make_float4(hh*hw*m*vy0*vx0, hh*lw*m*vy0*vx1,
                             lh*hw*m*vy1*vx0, lh*lw*m*vy1*vx1);
        sI[pl] = make_int4((iy0*64 + ix0) << 9, (iy0*64 + ix1) << 9,
                           (iy1*64 + ix0) << 9, (iy1*64 + ix1) << 9);
    }
    __syncthreads();

    const int wid = tid >> 5, lid = tid & 31;
    const int g  = wid & 3;                   // 64-channel group
    const int ph = wid >> 2;                  // px half (32)
    const char* xb = (const char*)g_xth + ((size_t)n << 21)   // n * 4096*512B
                   + g * 128 + lid * 4;
    const uint32_t stgb = (uint32_t)__cvta_generic_to_shared(stg) + wid * 4224;

    // ---- gather + lerp: lane = channel pair, 32 px ----
    #pragma unroll 4
    for (int j = 0; j < 32; j++) {
        int t = ph * 32 + j;
        float4 w = sW[t];
        int4   I = sI[t];
        float2 f0 = __half22float2(*(const __half2*)(xb + I.x));
        float2 f1 = __half22float2(*(const __half2*)(xb + I.y));
        float2 f2 = __half22float2(*(const __half2*)(xb + I.z));
        float2 f3 = __half22float2(*(const __half2*)(xb + I.w));
        float vx = w.x*f0.x + w.y*f1.x + w.z*f2.x + w.w*f3.x;
        float vy = w.x*f0.y + w.y*f1.y + w.z*f2.y + w.w*f3.y;
        __half2 hv = __floats2half2_rn(vx, vy);
        sts32(stgb + lid * 132 + j * 4, *(uint32_t*)&hv);
    }
    __syncwarp();

    // ---- de-interleave + store to g_colA (SW128 rows) ----
    // iteration p = channel pair; lanes: e = lid>>4 (even/odd ch), m = lid&15 (px pair)
    char* tb = (char*)g_colA + (size_t)tile * NCHK * 4096 + (size_t)(k * 8 + g * 2) * 4096;
    const int e = lid >> 4, m = lid & 15;
    const uint32_t sel = e ? 0x7632u : 0x5410u;
    #pragma unroll
    for (int p = 0; p < 32; p++) {
        uint32_t a = lds32(stgb + p * 132 + (2*m) * 4);
        uint32_t b = lds32(stgb + p * 132 + (2*m + 1) * 4);
        uint32_t v = prmt(a, b, sel);
        int c = 2 * p + e;                     // local channel 0..63
        int kcl = c & 31;
        char* cb = tb + (c >> 5) * 4096;
        *(uint32_t*)(cb + swz128((uint32_t)(kcl * 128 + (ph * 32 + 2*m) * 2))) = v;
    }
}

// ---------------------------------------------------------------------------
// fp16 mma GEMM: BM=64, 256 threads, 2 CTAs/SM, 4-stage bulk ring.
// A tile [32 kc][64 px] (4KB, SW128); B tile [256 oc][32 kc] (16KB, swz64).
// ---------------------------------------------------------------------------
#define A_TILE   4096
#define B_TILE   16384
#define STAGE_SZ (A_TILE + B_TILE)       // 20480
#define NSTAGE   4
#define MBAR_OFF (NSTAGE * STAGE_SZ)     // 81920
#define GEMM_SMEM (MBAR_OFF + 128)
#define STAGE_BYTES STAGE_SZ

__device__ __forceinline__ void bulk_g2s(uint32_t dst, const void* src,
                                         uint32_t bytes, uint32_t mbar) {
    asm volatile(
        "cp.async.bulk.shared::cluster.global.mbarrier::complete_tx::bytes "
        "[%0], [%1], %2, [%3];"
        :: "r"(dst), "l"(src), "r"(bytes), "r"(mbar) : "memory");
}
__device__ __forceinline__ void mbar_init(uint32_t a, uint32_t c) {
    asm volatile("mbarrier.init.shared.b64 [%0], %1;" :: "r"(a), "r"(c) : "memory");
}
__device__ __forceinline__ void mbar_expect(uint32_t a, uint32_t b) {
    asm volatile("mbarrier.arrive.expect_tx.shared.b64 _, [%0], %1;" :: "r"(a), "r"(b) : "memory");
}
__device__ __forceinline__ void mbar_arrive(uint32_t a) {
    asm volatile("mbarrier.arrive.shared.b64 _, [%0];" :: "r"(a) : "memory");
}
__device__ __forceinline__ void mbar_wait(uint32_t mbar, uint32_t parity) {
    uint32_t done;
    asm volatile("{\n\t.reg .pred p;\n\t"
        "mbarrier.try_wait.parity.acquire.cta.shared::cta.b64 p, [%1], %2;\n\t"
        "selp.b32 %0, 1, 0, p;\n\t}"
        : "=r"(done) : "r"(mbar), "r"(parity) : "memory");
    if (!done) {
        asm volatile("{\n\t.reg .pred P1;\n\t"
            "W_%=:\n\t"
            "mbarrier.try_wait.parity.acquire.cta.shared::cta.b64 P1, [%0], %1, 0x989680;\n\t"
            "@P1 bra.uni D_%=;\n\t"
            "bra.uni W_%=;\n\t"
            "D_%=:\n\t}" :: "r"(mbar), "r"(parity) : "memory");
    }
}

__global__ void __launch_bounds__(256, 2) gemm_bulk_kernel(float* __restrict__ out)
{
    extern __shared__ char sm[];
    const uint32_t sb = (uint32_t)__cvta_generic_to_shared(sm);
    const int tid = threadIdx.x;
    const int wid = tid >> 5, lid = tid & 31;
    const int warpM = wid & 1, warpN = wid >> 1;
    const int bm0 = blockIdx.x * 64;
    const int tile = blockIdx.x;

    if (tid == 0) {
        #pragma unroll
        for (int s = 0; s < NSTAGE; s++) {
            mbar_init(sb + MBAR_OFF + s*16, 1);
            mbar_init(sb + MBAR_OFF + s*16 + 8, 256);
        }
    }
    __syncthreads();

    float acc[2][8][4];
    #pragma unroll
    for (int i = 0; i < 2; i++)
        #pragma unroll
        for (int j = 0; j < 8; j++)
            #pragma unroll
            for (int q = 0; q < 4; q++) acc[i][j][q] = 0.f;

    const char* aSrc = (const char*)g_colA + (size_t)tile * NCHK * 4096;

    auto fill = [&](int f) {
        int s = f % NSTAGE;
        uint32_t base = sb + s * STAGE_SZ;
        uint32_t mb   = sb + MBAR_OFF + s * 16;
        mbar_expect(mb, STAGE_BYTES);
        bulk_g2s(base, aSrc + (size_t)f * 4096, A_TILE, mb);
        bulk_g2s(base + A_TILE, g_wtB + (size_t)f * 8192, B_TILE, mb);
    };

    if (tid == 0) {
        #pragma unroll
        for (int f = 0; f < NSTAGE - 1; f++) fill(f);
    }

    const int qq = lid >> 3;
    const int jr = lid & 7;
    // A: pitch 128B, SW128; pre-swizzle offset
    const uint32_t aoff = (uint32_t)(((qq >> 1) * 8 + jr) * 128
                                     + (warpM * 32 + (qq & 1) * 8) * 2);
    const int oc_lane = warpN * 64 + (qq >> 1) * 8 + jr;

    for (int ch = 0; ch < NCHK; ch++) {
        if (tid == 0) {
            int f = ch + NSTAGE - 1;
            if (f < NCHK) {
                if (f >= NSTAGE)
                    mbar_wait(sb + MBAR_OFF + (f % NSTAGE) * 16 + 8,
                              ((f / NSTAGE) - 1) & 1);
                fill(f);
            }
        }
        const int s = ch % NSTAGE;
        mbar_wait(sb + MBAR_OFF + s * 16, (ch / NSTAGE) & 1);

        const uint32_t ab = sb + s * STAGE_SZ;
        const uint32_t bb = ab + A_TILE;

        #pragma unroll
        for (int kp = 0; kp < 2; kp++) {
            uint32_t Af[2][4], Bf[4][4];
            #pragma unroll
            for (int mi = 0; mi < 2; mi++)
                ldmx4t(Af[mi], ab + swz128(aoff + kp * (16 * 128) + mi * 32));
            #pragma unroll
            for (int pi = 0; pi < 4; pi++) {
                uint32_t raw = (uint32_t)(oc_lane + pi * 16) * 64
                             + (kp * 2 + (qq & 1)) * 16;
                ldmx4(Bf[pi], bb + swz64(raw));
            }
            #pragma unroll
            for (int mi = 0; mi < 2; mi++)
                #pragma unroll
                for (int pi = 0; pi < 4; pi++) {
                    mma_f16(acc[mi][pi*2],   Af[mi], &Bf[pi][0]);
                    mma_f16(acc[mi][pi*2+1], Af[mi], &Bf[pi][2]);
                }
        }
        mbar_arrive(sb + MBAR_OFF + s * 16 + 8);
    }

    const int nIdx = bm0 >> 12;
    const int hwb  = bm0 & 4095;
    #pragma unroll
    for (int mi = 0; mi < 2; mi++) {
        int r = hwb + warpM * 32 + mi * 16 + (lid >> 2);
        #pragma unroll
        for (int jj = 0; jj < 8; jj++) {
            int oc = warpN * 64 + jj * 8 + (lid & 3) * 2;
            size_t base = ((size_t)(nIdx * OC + oc) << 12);
            out[base + r]            = acc[mi][jj][0];
            out[base + 4096 + r]     = acc[mi][jj][1];
            out[base + r + 8]        = acc[mi][jj][2];
            out[base + 4096 + r + 8] = acc[mi][jj][3];
        }
    }
}

// ---------------------------------------------------------------------------
extern "C" void kernel_launch(void* const* d_in, const int* in_sizes, int n_in,
                              void* d_out, int out_size)
{
    const float* x  = (const float*)d_in[0];
    const float* ow = (const float*)d_in[1];
    const float* ob = (const float*)d_in[2];
    const float* dw = (const float*)d_in[3];
    float* out = (float*)d_out;

    cudaFuncSetAttribute(gemm_bulk_kernel,
        cudaFuncAttributeMaxDynamicSharedMemorySize, GEMM_SMEM);

    prep_kernel<<<256 + NCHK, 256>>>(dw, ow);
    transpose_x_kernel<<<dim3(64, 4, 4), 256>>>(x);
    conv_gemm_kernel<<<NPIX/128, 256>>>(x, ob);
    sample4_kernel<<<dim3(NT64, 9), 256>>>();
    gemm_bulk_kernel<<<NT64, 256, GEMM_SMEM>>>(out);
}

// round 12
// speedup vs baseline: 1.3862x; 1.3862x over previous
#include <cuda_runtime.h>
#include <cuda_fp16.h>
#include <cstdint>

// Problem constants
#define N_B   4
#define C_IN  256
#define H_IM  64
#define W_IM  64
#define OC    256
#define K2    9
#define OMC   27
#define HW    (H_IM*W_IM)        // 4096
#define NPIX  (N_B*HW)           // 16384
#define KDIM  (C_IN*K2)          // 2304
#define NCHK  (KDIM/32)          // 72
#define NTILE (NPIX/128)         // 128

// ---------------- device scratch ----------------
__device__ float  g_om  [(size_t)N_B * OMC * HW];
__device__ __half g_colA[(size_t)NTILE * NCHK * 4096];  // tiled im2col: [tile][ch][32x128], swizzled
__device__ __half g_wtB [(size_t)NCHK * 8192];          // dcn weights, chunk-major, pre-swizzled
__device__ __half g_owB [(size_t)NCHK * 1024];          // offset weights, pre-swizzled

__device__ __host__ __forceinline__ uint32_t swz64(uint32_t a) {
    return a ^ (((a >> 7) & 3u) << 4);
}
__device__ __host__ __forceinline__ uint32_t swzA(uint32_t a) {
    return a ^ (((a >> 8) & 7u) << 4);
}

__device__ __forceinline__ void sts16(uint32_t addr, unsigned short v) {
    asm volatile("st.shared.u16 [%0], %1;" :: "r"(addr), "h"(v));
}
__device__ __forceinline__ void ldmx4(uint32_t* r, uint32_t addr) {
    asm volatile("ldmatrix.sync.aligned.m8n8.x4.shared.b16 {%0,%1,%2,%3}, [%4];"
        : "=r"(r[0]), "=r"(r[1]), "=r"(r[2]), "=r"(r[3]) : "r"(addr));
}
__device__ __forceinline__ void ldmx4t(uint32_t* r, uint32_t addr) {
    asm volatile("ldmatrix.sync.aligned.m8n8.x4.trans.shared.b16 {%0,%1,%2,%3}, [%4];"
        : "=r"(r[0]), "=r"(r[1]), "=r"(r[2]), "=r"(r[3]) : "r"(addr));
}
__device__ __forceinline__ void mma_f16(float* c, const uint32_t* a, const uint32_t* b) {
    asm volatile(
        "mma.sync.aligned.m16n8k16.row.col.f32.f16.f16.f32 "
        "{%0,%1,%2,%3}, {%4,%5,%6,%7}, {%8,%9}, {%0,%1,%2,%3};"
        : "+f"(c[0]), "+f"(c[1]), "+f"(c[2]), "+f"(c[3])
        : "r"(a[0]), "r"(a[1]), "r"(a[2]), "r"(a[3]), "r"(b[0]), "r"(b[1]));
}

// ---------------------------------------------------------------------------
// Prep: pack both weight tensors (fp16, chunk-major, pre-swizzled).
// ---------------------------------------------------------------------------
__global__ void prep_kernel(const float* __restrict__ dw,
                            const float* __restrict__ ow)
{
    if (blockIdx.x < 256) {
        int oc = blockIdx.x;
        int c  = threadIdx.x;
        #pragma unroll
        for (int k = 0; k < 9; k++) {
            float w = dw[((size_t)oc * C_IN + c) * K2 + k];
            int ch  = k * 8 + (c >> 5);
            int kcl = c & 31;
            uint32_t raw = (uint32_t)oc * 64 + kcl * 2;
            g_wtB[(size_t)ch * 8192 + (swz64(raw) >> 1)] = __float2half_rn(w);
        }
    } else {
        int ch = blockIdx.x - 256;
        int k  = ch >> 3;
        int c0 = (ch & 7) * 32;
        #pragma unroll
        for (int it = 0; it < 4; it++) {
            int idx = threadIdx.x + it * 256;
            int oc = idx >> 5, kcl = idx & 31;
            float w = (oc < OMC)
                ? ow[((size_t)oc * C_IN + c0 + kcl) * K2 + k] : 0.f;
            uint32_t raw = (uint32_t)oc * 64 + kcl * 2;
            g_owB[(size_t)ch * 1024 + (swz64(raw) >> 1)] = __float2half_rn(w);
        }
    }
}

// ---------------------------------------------------------------------------
// Offset conv as fp16 implicit GEMM, BM=64 (one ho row per CTA), 2 CTAs/SM.
// A tile [32 kc][64 px] pitch 144; B [32 oc][32 kc] swz64 (2KB).
// 8 warps = 4(M:16px) x 2(N:16oc). Double-buffered.
// ---------------------------------------------------------------------------
#define C2_AP   144
#define C2_A    (32 * C2_AP)       // 4608
#define C2_B    2048
#define C2_STG  (C2_A + C2_B)      // 6656

__global__ void __launch_bounds__(256, 2) conv_gemm_kernel(
    const float* __restrict__ x, const float* __restrict__ ob)
{
    __shared__ char sm[2 * C2_STG];
    const uint32_t sb = (uint32_t)__cvta_generic_to_shared(sm);
    const int tid = threadIdx.x;
    const int wid = tid >> 5, lid = tid & 31;
    const int bm0 = blockIdx.x * 64;
    const int nIdx = bm0 >> 12, hwb = bm0 & 4095, ho0 = hwb >> 6;
    const float* xn = x + ((size_t)nIdx * C_IN << 12);

    const int p  = tid & 63;          // px within row
    const int cq = tid >> 6;          // 0..3 base channel

    float acc[2][4];
    #pragma unroll
    for (int j = 0; j < 2; j++)
        #pragma unroll
        for (int q = 0; q < 4; q++) acc[j][q] = 0.f;

    auto build = [&](int ch, int st) {
        const int k = ch >> 3, c0 = (ch & 7) * 32;
        const int dy = k / 3 - 1, dx = k % 3 - 1;
        const int hy = ho0 + dy;
        const int wx = p + dx;
        const bool v = ((unsigned)hy < 64u) && ((unsigned)wx < 64u);
        const float* src = xn + ((size_t)(c0 + cq) << 12) + (hy << 6) + wx;
        const uint32_t dst = sb + st * C2_STG + cq * C2_AP + p * 2;
        #pragma unroll
        for (int it = 0; it < 8; it++) {
            float val = 0.f;
            if (v) val = src[(size_t)(it * 4) << 12];
            sts16(dst + it * 4 * C2_AP,
                  __half_as_ushort(__float2half_rn(val)));
        }
        if (tid < 128) {
            const uint4* bsrc = (const uint4*)(g_owB + (size_t)ch * 1024);
            *(uint4*)(sm + st * C2_STG + C2_A + tid * 16) = bsrc[tid];
        }
    };

    const int warpM = wid & 3, warpN = wid >> 2;
    const int qq = lid >> 3, jr = lid & 7;
    const uint32_t aoff = (uint32_t)(((qq >> 1) * 8 + jr) * C2_AP
                                     + (warpM * 16 + (qq & 1) * 8) * 2);
    const int oc_l = warpN * 16 + (qq >> 1) * 8 + jr;

    build(0, 0);
    __syncthreads();

    for (int ch = 0; ch < NCHK; ch++) {
        const int st = ch & 1;
        if (ch + 1 < NCHK) build(ch + 1, st ^ 1);

        const uint32_t ab = sb + st * C2_STG;
        const uint32_t bb = ab + C2_A;
        #pragma unroll
        for (int kp = 0; kp < 2; kp++) {
            uint32_t Af[4], Bf[4];
            ldmx4t(Af, ab + aoff + kp * (16 * C2_AP));
            uint32_t raw = (uint32_t)oc_l * 64 + (kp * 2 + (qq & 1)) * 16;
            ldmx4(Bf, bb + swz64(raw));
            mma_f16(acc[0], Af, &Bf[0]);
            mma_f16(acc[1], Af, &Bf[2]);
        }
        __syncthreads();
    }

    // epilogue: smem transpose -> coalesced g_om stores (+bias)
    float* T = (float*)sm;               // [32 oc][72]
    const int r0 = warpM * 16 + (lid >> 2);
    #pragma unroll
    for (int jj = 0; jj < 2; jj++) {
        int oc = warpN * 16 + jj * 8 + (lid & 3) * 2;
        T[ oc      * 72 + r0    ] = acc[jj][0];
        T[(oc + 1) * 72 + r0    ] = acc[jj][1];
        T[ oc      * 72 + r0 + 8] = acc[jj][2];
        T[(oc + 1) * 72 + r0 + 8] = acc[jj][3];
    }
    __syncthreads();
    for (int idx = tid; idx < OMC * 64; idx += 256) {
        int o = idx >> 6, m = idx & 63;
        g_om[((size_t)(nIdx * OMC + o) << 12) + hwb + m] = T[o * 72 + m] + ob[o];
    }
}

// ---------------------------------------------------------------------------
// Bilinear sampling -> tiled/swizzled g_colA (R8 version, verbatim)
// ---------------------------------------------------------------------------
__global__ void __launch_bounds__(256, 4) sample_kernel(const float* __restrict__ x)
{
    const int ho   = blockIdx.x;
    const int n    = blockIdx.y;
    const int half = blockIdx.z;
    const int tid  = threadIdx.x;

    __shared__ float s_w[K2][4][64];
    __shared__ int   s_idx[K2][4][64];

    for (int it = tid; it < 64 * K2; it += 256) {
        int k  = it / 64;
        int wo = it % 64;
        int p  = (ho << 6) + wo;
        const float* omn = g_om + (size_t)n * OMC * HW;

        float oy = omn[((size_t)(2*k    ) << 12) + p];
        float ox = omn[((size_t)(2*k + 1) << 12) + p];
        float mv = omn[((size_t)(18 + k ) << 12) + p];
        float m  = 1.0f / (1.0f + expf(-mv));

        float him = (float)(ho + (k / 3) - 1) + oy;
        float wim = (float)(wo + (k % 3) - 1) + ox;

        float y0 = floorf(him), x0 = floorf(wim);
        float lh = him - y0,    lw = wim - x0;
        float hh = 1.0f - lh,   hw = 1.0f - lw;
        float y1 = y0 + 1.0f,   x1 = x0 + 1.0f;

        float vy0 = (y0 >= 0.f && y0 <= 63.f) ? 1.f : 0.f;
        float vy1 = (y1 >= 0.f && y1 <= 63.f) ? 1.f : 0.f;
        float vx0 = (x0 >= 0.f && x0 <= 63.f) ? 1.f : 0.f;
        float vx1 = (x1 >= 0.f && x1 <= 63.f) ? 1.f : 0.f;

        int iy0 = (int)fminf(fmaxf(y0, 0.f), 63.f);
        int iy1 = (int)fminf(fmaxf(y1, 0.f), 63.f);
        int ix0 = (int)fminf(fmaxf(x0, 0.f), 63.f);
        int ix1 = (int)fminf(fmaxf(x1, 0.f), 63.f);

        s_w[k][0][wo] = hh * hw * m * vy0 * vx0;  s_idx[k][0][wo] = iy0 * 64 + ix0;
        s_w[k][1][wo] = hh * lw * m * vy0 * vx1;  s_idx[k][1][wo] = iy0 * 64 + ix1;
        s_w[k][2][wo] = lh * hw * m * vy1 * vx0;  s_idx[k][2][wo] = iy1 * 64 + ix0;
        s_w[k][3][wo] = lh * lw * m * vy1 * vx1;  s_idx[k][3][wo] = iy1 * 64 + ix1;
    }
    __syncthreads();

    const int wo = tid & 63;
    const int cq = tid >> 6;
    const int pg   = (n << 12) + (ho << 6) + wo;   // global pixel
    const int tile = pg >> 7;
    const int pl   = pg & 127;
    const float* xnn = x + (((size_t)(n * C_IN) + half * 128 + cq) << 12);
    char* tbase = (char*)g_colA + (size_t)tile * NCHK * 8192;

    #pragma unroll
    for (int k = 0; k < K2; k++) {
        float w0 = s_w[k][0][wo], w1 = s_w[k][1][wo];
        float w2 = s_w[k][2][wo], w3 = s_w[k][3][wo];
        int i0 = s_idx[k][0][wo], i1 = s_idx[k][1][wo];
        int i2 = s_idx[k][2][wo], i3 = s_idx[k][3][wo];
        const float* xb = xnn;
        #pragma unroll 4
        for (int ci = 0; ci < 32; ci++) {
            int c = half * 128 + ci * 4 + cq;
            int ch = k * 8 + (c >> 5);
            int kcl = c & 31;
            float v = w0 * xb[i0] + w1 * xb[i1] + w2 * xb[i2] + w3 * xb[i3];
            *(__half*)(tbase + (size_t)ch * 8192 + swzA(kcl * 256 + pl * 2))
                = __float2half_rn(v);
            xb += 4 * HW;
        }
    }
}

// ---------------------------------------------------------------------------
// fp16 mma GEMM: contiguous bulk staging, 4 stages, BM=128 (R8 version)
// ---------------------------------------------------------------------------
#define A_TILE   8192
#define B_TILE   16384
#define STAGE_SZ (A_TILE + B_TILE)
#define NSTAGE   4
#define MBAR_OFF (NSTAGE * STAGE_SZ)
#define GEMM_SMEM (MBAR_OFF + 128)
#define STAGE_BYTES STAGE_SZ

__device__ __forceinline__ void bulk_g2s(uint32_t dst, const void* src,
                                         uint32_t bytes, uint32_t mbar) {
    asm volatile(
        "cp.async.bulk.shared::cluster.global.mbarrier::complete_tx::bytes "
        "[%0], [%1], %2, [%3];"
        :: "r"(dst), "l"(src), "r"(bytes), "r"(mbar) : "memory");
}
__device__ __forceinline__ void mbar_init(uint32_t a, uint32_t c) {
    asm volatile("mbarrier.init.shared.b64 [%0], %1;" :: "r"(a), "r"(c) : "memory");
}
__device__ __forceinline__ void mbar_expect(uint32_t a, uint32_t b) {
    asm volatile("mbarrier.arrive.expect_tx.shared.b64 _, [%0], %1;" :: "r"(a), "r"(b) : "memory");
}
__device__ __forceinline__ void mbar_arrive(uint32_t a) {
    asm volatile("mbarrier.arrive.shared.b64 _, [%0];" :: "r"(a) : "memory");
}
__device__ __forceinline__ void mbar_wait(uint32_t mbar, uint32_t parity) {
    uint32_t done;
    asm volatile("{\n\t.reg .pred p;\n\t"
        "mbarrier.try_wait.parity.acquire.cta.shared::cta.b64 p, [%1], %2;\n\t"
        "selp.b32 %0, 1, 0, p;\n\t}"
        : "=r"(done) : "r"(mbar), "r"(parity) : "memory");
    if (!done) {
        asm volatile("{\n\t.reg .pred P1;\n\t"
            "W_%=:\n\t"
            "mbarrier.try_wait.parity.acquire.cta.shared::cta.b64 P1, [%0], %1, 0x989680;\n\t"
            "@P1 bra.uni D_%=;\n\t"
            "bra.uni W_%=;\n\t"
            "D_%=:\n\t}" :: "r"(mbar), "r"(parity) : "memory");
    }
}

__global__ void __launch_bounds__(512, 1) gemm_bulk_kernel(float* __restrict__ out)
{
    extern __shared__ char sm[];
    const uint32_t sb = (uint32_t)__cvta_generic_to_shared(sm);
    const int tid = threadIdx.x;
    const int wid = tid >> 5, lid = tid & 31;
    const int warpM = wid & 3, warpN = wid >> 2;
    const int bm0 = blockIdx.x * 128;
    const int tile = blockIdx.x;

    if (tid == 0) {
        #pragma unroll
        for (int s = 0; s < NSTAGE; s++) {
            mbar_init(sb + MBAR_OFF + s*16, 1);
            mbar_init(sb + MBAR_OFF + s*16 + 8, 512);
        }
    }
    __syncthreads();

    float acc[2][8][4];
    #pragma unroll
    for (int i = 0; i < 2; i++)
        #pragma unroll
        for (int j = 0; j < 8; j++)
            #pragma unroll
            for (int q = 0; q < 4; q++) acc[i][j][q] = 0.f;

    const char* aSrc = (const char*)g_colA + (size_t)tile * NCHK * 8192;

    auto fill = [&](int f) {
        int s = f % NSTAGE;
        uint32_t base = sb + s * STAGE_SZ;
        uint32_t mb   = sb + MBAR_OFF + s * 16;
        mbar_expect(mb, STAGE_BYTES);
        bulk_g2s(base, aSrc + (size_t)f * 8192, A_TILE, mb);
        bulk_g2s(base + A_TILE, g_wtB + (size_t)f * 8192, B_TILE, mb);
    };

    if (tid == 0) {
        #pragma unroll
        for (int f = 0; f < NSTAGE - 1; f++) fill(f);
    }

    const int qq = lid >> 3;
    const int jr = lid & 7;
    const uint32_t aoff = (uint32_t)(((qq >> 1) * 8 + jr) * 256
                                     + (warpM * 32 + (qq & 1) * 8) * 2);
    const int oc_lane = warpN * 64 + (qq >> 1) * 8 + jr;

    for (int ch = 0; ch < NCHK; ch++) {
        if (tid == 0) {
            int f = ch + NSTAGE - 1;
            if (f < NCHK) {
                if (f >= NSTAGE)
                    mbar_wait(sb + MBAR_OFF + (f % NSTAGE) * 16 + 8,
                              ((f / NSTAGE) - 1) & 1);
                fill(f);
            }
        }
        const int s = ch % NSTAGE;
        mbar_wait(sb + MBAR_OFF + s * 16, (ch / NSTAGE) & 1);

        const uint32_t ab = sb + s * STAGE_SZ;
        const uint32_t bb = ab + A_TILE;

        #pragma unroll
        for (int kp = 0; kp < 2; kp++) {
            uint32_t Af[2][4], Bf[4][4];
            #pragma unroll
            for (int mi = 0; mi < 2; mi++)
                ldmx4t(Af[mi], ab + swzA(aoff + kp * (16 * 256) + mi * 32));
            #pragma unroll
            for (int pi = 0; pi < 4; pi++) {
                uint32_t raw = (uint32_t)(oc_lane + pi * 16) * 64
                             + (kp * 2 + (qq & 1)) * 16;
                ldmx4(Bf[pi], bb + swz64(raw));
            }
            #pragma unroll
            for (int mi = 0; mi < 2; mi++)
                #pragma unroll
                for (int pi = 0; pi < 4; pi++) {
                    mma_f16(acc[mi][pi*2],   Af[mi], &Bf[pi][0]);
                    mma_f16(acc[mi][pi*2+1], Af[mi], &Bf[pi][2]);
                }
        }
        mbar_arrive(sb + MBAR_OFF + s * 16 + 8);
    }

    const int nIdx = bm0 >> 12;
    const int hwb  = bm0 & 4095;
    #pragma unroll
    for (int mi = 0; mi < 2; mi++) {
        int r = hwb + warpM * 32 + mi * 16 + (lid >> 2);
        #pragma unroll
        for (int jj = 0; jj < 8; jj++) {
            int oc = warpN * 64 + jj * 8 + (lid & 3) * 2;
            size_t base = ((size_t)(nIdx * OC + oc) << 12);
            out[base + r]            = acc[mi][jj][0];
            out[base + 4096 + r]     = acc[mi][jj][1];
            out[base + r + 8]        = acc[mi][jj][2];
            out[base + 4096 + r + 8] = acc[mi][jj][3];
        }
    }
}

// ---------------------------------------------------------------------------
extern "C" void kernel_launch(void* const* d_in, const int* in_sizes, int n_in,
                              void* d_out, int out_size)
{
    const float* x  = (const float*)d_in[0];
    const float* ow = (const float*)d_in[1];
    const float* ob = (const float*)d_in[2];
    const float* dw = (const float*)d_in[3];
    float* out = (float*)d_out;

    cudaFuncSetAttribute(gemm_bulk_kernel,
        cudaFuncAttributeMaxDynamicSharedMemorySize, GEMM_SMEM);

    prep_kernel<<<256 + NCHK, 256>>>(dw, ow);
    conv_gemm_kernel<<<NPIX/64, 256>>>(x, ob);
    sample_kernel<<<dim3(H_IM, N_B, 2), 256>>>(x);
    gemm_bulk_kernel<<<NPIX/128, 512, GEMM_SMEM>>>(out);
}

// round 13
// speedup vs baseline: 1.6129x; 1.1636x over previous
#include <cuda_runtime.h>
#include <cuda_fp16.h>
#include <cstdint>

// Problem constants
#define N_B   4
#define C_IN  256
#define H_IM  64
#define W_IM  64
#define OC    256
#define K2    9
#define OMC   27
#define HW    (H_IM*W_IM)        // 4096
#define NPIX  (N_B*HW)           // 16384
#define KDIM  (C_IN*K2)          // 2304
#define NCHK  (KDIM/32)          // 72
#define NTILE (NPIX/128)         // 128

// ---------------- device scratch ----------------
__device__ float  g_om  [(size_t)N_B * OMC * HW];
__device__ __half g_xth [(size_t)NPIX * C_IN];          // x transposed fp16: [n][hw][c]
__device__ __half g_colA[(size_t)NTILE * NCHK * 4096];  // im2col: [tile][ch][128px x 32kc], swz64
__device__ __half g_wtB [(size_t)NCHK * 8192];          // dcn weights, chunk-major, swz64
__device__ __half g_owB [(size_t)NCHK * 1024];          // offset weights, swz64

__device__ __host__ __forceinline__ uint32_t swz64(uint32_t a) {
    return a ^ (((a >> 7) & 3u) << 4);
}

__device__ __forceinline__ void sts16(uint32_t addr, unsigned short v) {
    asm volatile("st.shared.u16 [%0], %1;" :: "r"(addr), "h"(v));
}
__device__ __forceinline__ void ldmx4(uint32_t* r, uint32_t addr) {
    asm volatile("ldmatrix.sync.aligned.m8n8.x4.shared.b16 {%0,%1,%2,%3}, [%4];"
        : "=r"(r[0]), "=r"(r[1]), "=r"(r[2]), "=r"(r[3]) : "r"(addr));
}
__device__ __forceinline__ void ldmx4t(uint32_t* r, uint32_t addr) {
    asm volatile("ldmatrix.sync.aligned.m8n8.x4.trans.shared.b16 {%0,%1,%2,%3}, [%4];"
        : "=r"(r[0]), "=r"(r[1]), "=r"(r[2]), "=r"(r[3]) : "r"(addr));
}
__device__ __forceinline__ void mma_f16(float* c, const uint32_t* a, const uint32_t* b) {
    asm volatile(
        "mma.sync.aligned.m16n8k16.row.col.f32.f16.f16.f32 "
        "{%0,%1,%2,%3}, {%4,%5,%6,%7}, {%8,%9}, {%0,%1,%2,%3};"
        : "+f"(c[0]), "+f"(c[1]), "+f"(c[2]), "+f"(c[3])
        : "r"(a[0]), "r"(a[1]), "r"(a[2]), "r"(a[3]), "r"(b[0]), "r"(b[1]));
}

// ---------------------------------------------------------------------------
// Prep: pack both weight tensors (fp16, chunk-major, pre-swizzled).
// ---------------------------------------------------------------------------
__global__ void prep_kernel(const float* __restrict__ dw,
                            const float* __restrict__ ow)
{
    if (blockIdx.x < 256) {
        int oc = blockIdx.x;
        int c  = threadIdx.x;
        #pragma unroll
        for (int k = 0; k < 9; k++) {
            float w = dw[((size_t)oc * C_IN + c) * K2 + k];
            int ch  = k * 8 + (c >> 5);
            int kcl = c & 31;
            uint32_t raw = (uint32_t)oc * 64 + kcl * 2;
            g_wtB[(size_t)ch * 8192 + (swz64(raw) >> 1)] = __float2half_rn(w);
        }
    } else {
        int ch = blockIdx.x - 256;
        int k  = ch >> 3;
        int c0 = (ch & 7) * 32;
        #pragma unroll
        for (int it = 0; it < 4; it++) {
            int idx = threadIdx.x + it * 256;
            int oc = idx >> 5, kcl = idx & 31;
            float w = (oc < OMC)
                ? ow[((size_t)oc * C_IN + c0 + kcl) * K2 + k] : 0.f;
            uint32_t raw = (uint32_t)oc * 64 + kcl * 2;
            g_owB[(size_t)ch * 1024 + (swz64(raw) >> 1)] = __float2half_rn(w);
        }
    }
}

// ---------------------------------------------------------------------------
// Transpose x [n][c][hw] -> g_xth [n][hw][c] (fp16)
// ---------------------------------------------------------------------------
__global__ void transpose_x_kernel(const float* __restrict__ x)
{
    __shared__ float ts[64][65];
    const int hw0 = blockIdx.x * 64, c0 = blockIdx.y * 64, n = blockIdx.z;
    const float* xn = x + ((size_t)(n * C_IN + c0) << 12) + hw0;
    for (int i = threadIdx.x; i < 64 * 64; i += 256) {
        int r = i >> 6, col = i & 63;
        ts[r][col] = xn[((size_t)r << 12) + col];
    }
    __syncthreads();
    __half* xtn = g_xth + (((size_t)n << 12) + hw0) * C_IN + c0;
    for (int i = threadIdx.x; i < 64 * 64; i += 256) {
        int r = i >> 6, col = i & 63;
        xtn[(size_t)r * C_IN + col] = __float2half_rn(ts[col][r]);
    }
}

// ---------------------------------------------------------------------------
// Offset conv as fp16 implicit GEMM, BM=64, 2 CTAs/SM (R12 version, verbatim)
// ---------------------------------------------------------------------------
#define C2_AP   144
#define C2_A    (32 * C2_AP)
#define C2_B    2048
#define C2_STG  (C2_A + C2_B)

__global__ void __launch_bounds__(256, 2) conv_gemm_kernel(
    const float* __restrict__ x, const float* __restrict__ ob)
{
    __shared__ char sm[2 * C2_STG];
    const uint32_t sb = (uint32_t)__cvta_generic_to_shared(sm);
    const int tid = threadIdx.x;
    const int wid = tid >> 5, lid = tid & 31;
    const int bm0 = blockIdx.x * 64;
    const int nIdx = bm0 >> 12, hwb = bm0 & 4095, ho0 = hwb >> 6;
    const float* xn = x + ((size_t)nIdx * C_IN << 12);

    const int p  = tid & 63;
    const int cq = tid >> 6;

    float acc[2][4];
    #pragma unroll
    for (int j = 0; j < 2; j++)
        #pragma unroll
        for (int q = 0; q < 4; q++) acc[j][q] = 0.f;

    auto build = [&](int ch, int st) {
        const int k = ch >> 3, c0 = (ch & 7) * 32;
        const int dy = k / 3 - 1, dx = k % 3 - 1;
        const int hy = ho0 + dy;
        const int wx = p + dx;
        const bool v = ((unsigned)hy < 64u) && ((unsigned)wx < 64u);
        const float* src = xn + ((size_t)(c0 + cq) << 12) + (hy << 6) + wx;
        const uint32_t dst = sb + st * C2_STG + cq * C2_AP + p * 2;
        #pragma unroll
        for (int it = 0; it < 8; it++) {
            float val = 0.f;
            if (v) val = src[(size_t)(it * 4) << 12];
            sts16(dst + it * 4 * C2_AP,
                  __half_as_ushort(__float2half_rn(val)));
        }
        if (tid < 128) {
            const uint4* bsrc = (const uint4*)(g_owB + (size_t)ch * 1024);
            *(uint4*)(sm + st * C2_STG + C2_A + tid * 16) = bsrc[tid];
        }
    };

    const int warpM = wid & 3, warpN = wid >> 2;
    const int qq = lid >> 3, jr = lid & 7;
    const uint32_t aoff = (uint32_t)(((qq >> 1) * 8 + jr) * C2_AP
                                     + (warpM * 16 + (qq & 1) * 8) * 2);
    const int oc_l = warpN * 16 + (qq >> 1) * 8 + jr;

    build(0, 0);
    __syncthreads();

    for (int ch = 0; ch < NCHK; ch++) {
        const int st = ch & 1;
        if (ch + 1 < NCHK) build(ch + 1, st ^ 1);

        const uint32_t ab = sb + st * C2_STG;
        const uint32_t bb = ab + C2_A;
        #pragma unroll
        for (int kp = 0; kp < 2; kp++) {
            uint32_t Af[4], Bf[4];
            ldmx4t(Af, ab + aoff + kp * (16 * C2_AP));
            uint32_t raw = (uint32_t)oc_l * 64 + (kp * 2 + (qq & 1)) * 16;
            ldmx4(Bf, bb + swz64(raw));
            mma_f16(acc[0], Af, &Bf[0]);
            mma_f16(acc[1], Af, &Bf[2]);
        }
        __syncthreads();
    }

    float* T = (float*)sm;
    const int r0 = warpM * 16 + (lid >> 2);
    #pragma unroll
    for (int jj = 0; jj < 2; jj++) {
        int oc = warpN * 16 + jj * 8 + (lid & 3) * 2;
        T[ oc      * 72 + r0    ] = acc[jj][0];
        T[(oc + 1) * 72 + r0    ] = acc[jj][1];
        T[ oc      * 72 + r0 + 8] = acc[jj][2];
        T[(oc + 1) * 72 + r0 + 8] = acc[jj][3];
    }
    __syncthreads();
    for (int idx = tid; idx < OMC * 64; idx += 256) {
        int o = idx >> 6, m = idx & 63;
        g_om[((size_t)(nIdx * OMC + o) << 12) + hwb + m] = T[o * 72 + m] + ob[o];
    }
}

// ---------------------------------------------------------------------------
// Sampling v5: half2 channel-major gathers, direct u32 stores into [px][kc]
// rows (swz64). grid (128 tiles, 9 taps), 256 threads = 8 warps.
// Warp w: ch-group g = w&3 (64 ch; lane = ch pair), px-half ph = w>>2 (64 px).
// ---------------------------------------------------------------------------
__global__ void __launch_bounds__(256, 6) sample5_kernel()
{
    __shared__ float4 sW[128];
    __shared__ int4   sI[128];              // byte offsets (hw * 512)

    const int tile = blockIdx.x;
    const int k    = blockIdx.y;
    const int n    = tile >> 5;
    const int hw0  = (tile & 31) * 128;
    const int tid  = threadIdx.x;

    const float* omn = g_om + (size_t)n * OMC * HW;
    if (tid < 128) {
        int pl = tid;
        int p = hw0 + pl;
        int ho = p >> 6, wo = p & 63;

        float oy = omn[((size_t)(2*k    ) << 12) + p];
        float ox = omn[((size_t)(2*k + 1) << 12) + p];
        float mv = omn[((size_t)(18 + k ) << 12) + p];
        float m  = 1.0f / (1.0f + expf(-mv));

        float him = (float)(ho + (k / 3) - 1) + oy;
        float wim = (float)(wo + (k % 3) - 1) + ox;

        float y0 = floorf(him), x0 = floorf(wim);
        float lh = him - y0,    lw = wim - x0;
        float hh = 1.0f - lh,   hw = 1.0f - lw;
        float y1 = y0 + 1.0f,   x1 = x0 + 1.0f;

        float vy0 = (y0 >= 0.f && y0 <= 63.f) ? 1.f : 0.f;
        float vy1 = (y1 >= 0.f && y1 <= 63.f) ? 1.f : 0.f;
        float vx0 = (x0 >= 0.f && x0 <= 63.f) ? 1.f : 0.f;
        float vx1 = (x1 >= 0.f && x1 <= 63.f) ? 1.f : 0.f;

        int iy0 = (int)fminf(fmaxf(y0, 0.f), 63.f);
        int iy1 = (int)fminf(fmaxf(y1, 0.f), 63.f);
        int ix0 = (int)fminf(fmaxf(x0, 0.f), 63.f);
        int ix1 = (int)fminf(fmaxf(x1, 0.f), 63.f);

        sW[pl] = make_float4(hh*hw*m*vy0*vx0, hh*lw*m*vy0*vx1,
                             lh*hw*m*vy1*vx0, lh*lw*m*vy1*vx1);
        sI[pl] = make_int4((iy0*64 + ix0) << 9, (iy0*64 + ix1) << 9,
                           (iy1*64 + ix0) << 9, (iy1*64 + ix1) << 9);
    }
    __syncthreads();

    const int wid = tid >> 5, lid = tid & 31;
    const int g  = wid & 3;                  // 64-channel group
    const int ph = wid >> 2;                 // px half
    // lane's channel pair: c0 = g*64 + 2*lid
    const char* xb = (const char*)g_xth + ((size_t)n << 21) + g * 128 + lid * 4;
    // dest chunk = k*8 + g*2 + (lid>>4); kcl = (2*lid)&31
    char* cb = (char*)g_colA + (size_t)tile * NCHK * 8192
             + (size_t)(k * 8 + g * 2 + (lid >> 4)) * 8192;
    const uint32_t colb = (uint32_t)((2 * lid) & 31) * 2;

    #pragma unroll 4
    for (int j = 0; j < 64; j++) {
        int pl = ph * 64 + j;
        float4 w = sW[pl];
        int4   I = sI[pl];
        float2 f0 = __half22float2(*(const __half2*)(xb + I.x));
        float2 f1 = __half22float2(*(const __half2*)(xb + I.y));
        float2 f2 = __half22float2(*(const __half2*)(xb + I.z));
        float2 f3 = __half22float2(*(const __half2*)(xb + I.w));
        float vx = w.x*f0.x + w.y*f1.x + w.z*f2.x + w.w*f3.x;
        float vy = w.x*f0.y + w.y*f1.y + w.z*f2.y + w.w*f3.y;
        __half2 hv = __floats2half2_rn(vx, vy);
        *(uint32_t*)(cb + swz64((uint32_t)pl * 64 + colb)) = *(uint32_t*)&hv;
    }
}

// ---------------------------------------------------------------------------
// fp16 mma GEMM: bulk staging, 4 stages, BM=128. A now [128px][32kc] swz64,
// fragments via NON-trans ldmatrix (q0:m0k0, q1:m8k0, q2:m0k8, q3:m8k8).
// ---------------------------------------------------------------------------
#define A_TILE   8192
#define B_TILE   16384
#define STAGE_SZ (A_TILE + B_TILE)
#define NSTAGE   4
#define MBAR_OFF (NSTAGE * STAGE_SZ)
#define GEMM_SMEM (MBAR_OFF + 128)
#define STAGE_BYTES STAGE_SZ

__device__ __forceinline__ void bulk_g2s(uint32_t dst, const void* src,
                                         uint32_t bytes, uint32_t mbar) {
    asm volatile(
        "cp.async.bulk.shared::cluster.global.mbarrier::complete_tx::bytes "
        "[%0], [%1], %2, [%3];"
        :: "r"(dst), "l"(src), "r"(bytes), "r"(mbar) : "memory");
}
__device__ __forceinline__ void mbar_init(uint32_t a, uint32_t c) {
    asm volatile("mbarrier.init.shared.b64 [%0], %1;" :: "r"(a), "r"(c) : "memory");
}
__device__ __forceinline__ void mbar_expect(uint32_t a, uint32_t b) {
    asm volatile("mbarrier.arrive.expect_tx.shared.b64 _, [%0], %1;" :: "r"(a), "r"(b) : "memory");
}
__device__ __forceinline__ void mbar_arrive(uint32_t a) {
    asm volatile("mbarrier.arrive.shared.b64 _, [%0];" :: "r"(a) : "memory");
}
__device__ __forceinline__ void mbar_wait(uint32_t mbar, uint32_t parity) {
    uint32_t done;
    asm volatile("{\n\t.reg .pred p;\n\t"
        "mbarrier.try_wait.parity.acquire.cta.shared::cta.b64 p, [%1], %2;\n\t"
        "selp.b32 %0, 1, 0, p;\n\t}"
        : "=r"(done) : "r"(mbar), "r"(parity) : "memory");
    if (!done) {
        asm volatile("{\n\t.reg .pred P1;\n\t"
            "W_%=:\n\t"
            "mbarrier.try_wait.parity.acquire.cta.shared::cta.b64 P1, [%0], %1, 0x989680;\n\t"
            "@P1 bra.uni D_%=;\n\t"
            "bra.uni W_%=;\n\t"
            "D_%=:\n\t}" :: "r"(mbar), "r"(parity) : "memory");
    }
}

__global__ void __launch_bounds__(512, 1) gemm_bulk_kernel(float* __restrict__ out)
{
    extern __shared__ char sm[];
    const uint32_t sb = (uint32_t)__cvta_generic_to_shared(sm);
    const int tid = threadIdx.x;
    const int wid = tid >> 5, lid = tid & 31;
    const int warpM = wid & 3, warpN = wid >> 2;
    const int bm0 = blockIdx.x * 128;
    const int tile = blockIdx.x;

    if (tid == 0) {
        #pragma unroll
        for (int s = 0; s < NSTAGE; s++) {
            mbar_init(sb + MBAR_OFF + s*16, 1);
            mbar_init(sb + MBAR_OFF + s*16 + 8, 512);
        }
    }
    __syncthreads();

    float acc[2][8][4];
    #pragma unroll
    for (int i = 0; i < 2; i++)
        #pragma unroll
        for (int j = 0; j < 8; j++)
            #pragma unroll
            for (int q = 0; q < 4; q++) acc[i][j][q] = 0.f;

    const char* aSrc = (const char*)g_colA + (size_t)tile * NCHK * 8192;

    auto fill = [&](int f) {
        int s = f % NSTAGE;
        uint32_t base = sb + s * STAGE_SZ;
        uint32_t mb   = sb + MBAR_OFF + s * 16;
        mbar_expect(mb, STAGE_BYTES);
        bulk_g2s(base, aSrc + (size_t)f * 8192, A_TILE, mb);
        bulk_g2s(base + A_TILE, g_wtB + (size_t)f * 8192, B_TILE, mb);
    };

    if (tid == 0) {
        #pragma unroll
        for (int f = 0; f < NSTAGE - 1; f++) fill(f);
    }

    const int qq = lid >> 3;
    const int jr = lid & 7;
    // A rows 64B: row = warpM*32 + mi*16 + (qq&1)*8 + jr ; col = (qq>>1)*16 + kp*32
    const uint32_t aoff_raw = (uint32_t)((warpM * 32 + (qq & 1) * 8 + jr) * 64
                                         + (qq >> 1) * 16);
    const int oc_lane = warpN * 64 + (qq >> 1) * 8 + jr;

    for (int ch = 0; ch < NCHK; ch++) {
        if (tid == 0) {
            int f = ch + NSTAGE - 1;
            if (f < NCHK) {
                if (f >= NSTAGE)
                    mbar_wait(sb + MBAR_OFF + (f % NSTAGE) * 16 + 8,
                              ((f / NSTAGE) - 1) & 1);
                fill(f);
            }
        }
        const int s = ch % NSTAGE;
        mbar_wait(sb + MBAR_OFF + s * 16, (ch / NSTAGE) & 1);

        const uint32_t ab = sb + s * STAGE_SZ;
        const uint32_t bb = ab + A_TILE;

        #pragma unroll
        for (int kp = 0; kp < 2; kp++) {
            uint32_t Af[2][4], Bf[4][4];
            #pragma unroll
            for (int mi = 0; mi < 2; mi++)
                ldmx4(Af[mi], ab + swz64(aoff_raw + mi * 1024 + kp * 32));
            #pragma unroll
            for (int pi = 0; pi < 4; pi++) {
                uint32_t raw = (uint32_t)(oc_lane + pi * 16) * 64
                             + (kp * 2 + (qq & 1)) * 16;
                ldmx4(Bf[pi], bb + swz64(raw));
            }
            #pragma unroll
            for (int mi = 0; mi < 2; mi++)
                #pragma unroll
                for (int pi = 0; pi < 4; pi++) {
                    mma_f16(acc[mi][pi*2],   Af[mi], &Bf[pi][0]);
                    mma_f16(acc[mi][pi*2+1], Af[mi], &Bf[pi][2]);
                }
        }
        mbar_arrive(sb + MBAR_OFF + s * 16 + 8);
    }

    const int nIdx = bm0 >> 12;
    const int hwb  = bm0 & 4095;
    #pragma unroll
    for (int mi = 0; mi < 2; mi++) {
        int r = hwb + warpM * 32 + mi * 16 + (lid >> 2);
        #pragma unroll
        for (int jj = 0; jj < 8; jj++) {
            int oc = warpN * 64 + jj * 8 + (lid & 3) * 2;
            size_t base = ((size_t)(nIdx * OC + oc) << 12);
            out[base + r]            = acc[mi][jj][0];
            out[base + 4096 + r]     = acc[mi][jj][1];
            out[base + r + 8]        = acc[mi][jj][2];
            out[base + 4096 + r + 8] = acc[mi][jj][3];
        }
    }
}

// ---------------------------------------------------------------------------
extern "C" void kernel_launch(void* const* d_in, const int* in_sizes, int n_in,
                              void* d_out, int out_size)
{
    const float* x  = (const float*)d_in[0];
    const float* ow = (const float*)d_in[1];
    const float* ob = (const float*)d_in[2];
    const float* dw = (const float*)d_in[3];
    float* out = (float*)d_out;

    cudaFuncSetAttribute(gemm_bulk_kernel,
        cudaFuncAttributeMaxDynamicSharedMemorySize, GEMM_SMEM);

    prep_kernel<<<256 + NCHK, 256>>>(dw, ow);
    transpose_x_kernel<<<dim3(64, 4, 4), 256>>>(x);
    conv_gemm_kernel<<<NPIX/64, 256>>>(x, ob);
    sample5_kernel<<<dim3(NTILE, 9), 256>>>();
    gemm_bulk_kernel<<<NPIX/128, 512, GEMM_SMEM>>>(out);
}